// round 2
// baseline (speedup 1.0000x reference)
#include <cuda_runtime.h>
#include <cstdint>
#include <cstddef>

// ---------------- static problem shape ----------------
constexpr int BSZ = 2;
constexpr int NQ  = 21760;
constexpr int MR  = BSZ * NQ;      // 43520 rows
constexpr int D   = 256;
constexpr int NH  = 8;
constexpr int DH  = 32;
constexpr int NFUSED = 384;        // 256 offs + 128 attn logits

__device__ __constant__ int c_LW[4] = {128, 64, 32, 16};
__device__ __constant__ int c_LH[4] = {128, 64, 32, 16};
__device__ __constant__ int c_LS[4] = {0, 16384, 20480, 21504};

// ---------------- scratch (device globals; no allocation allowed) ----------------
__device__ float  g_vt[(size_t)BSZ * NH * NQ * DH];     // v transposed: [b][h][pos][c]
__device__ float  g_P [(size_t)MR * NFUSED];            // raw offs(256) + attn logits(128)
__device__ float4 g_samp[(size_t)MR * NH * 16];         // (x_px, y_px, weight, 0) per point
__device__ float  g_tmp[(size_t)MR * D];                // attention output before Wout
__device__ float  g_Wf[D * NFUSED];                     // fused [Wo | Wa]
__device__ float  g_bf[NFUSED];                         // fused [bo | ba]

// ---------------- pack fused weight ----------------
__global__ void pack_w_kernel(const float* __restrict__ Wo, const float* __restrict__ bo,
                              const float* __restrict__ Wa, const float* __restrict__ ba) {
    int i = blockIdx.x * blockDim.x + threadIdx.x;
    if (i < D * NFUSED) {
        int k = i / NFUSED, n = i % NFUSED;
        g_Wf[i] = (n < 256) ? Wo[k * 256 + n] : Wa[k * 128 + (n - 256)];
    }
    if (i < NFUSED) g_bf[i] = (i < 256) ? bo[i] : ba[i - 256];
}

// ---------------- generic tiled fp32 GEMM: C = A[M,K] @ W[K,N] + bias (+epilogue) ----------------
// MODE 0: A=value, W=Wv -> store into g_vt with (b,h,pos,c) layout
// MODE 1: A=query, W=g_Wf -> store g_P row-major
// MODE 2: A=g_tmp, W=Wout -> store Cout = acc + bias + addin (residual)
template<int MODE>
__global__ __launch_bounds__(256)
void gemm_kernel(const float* __restrict__ Ain, const float* __restrict__ Win,
                 const float* __restrict__ biasin, const float* __restrict__ addin,
                 float* __restrict__ Cout, int N)
{
    constexpr int K = D;
    const float* A    = (MODE == 2) ? g_tmp : Ain;
    const float* W    = (MODE == 1) ? g_Wf  : Win;
    const float* bias = (MODE == 1) ? g_bf  : biasin;

    __shared__ float As[16][132];   // [k][m], padded
    __shared__ float Bs[16][64];    // [k][n]

    const int tid = threadIdx.x;
    const int ty  = tid >> 4;       // 0..15
    const int tx  = tid & 15;       // 0..15
    const int m0  = blockIdx.x * 128;
    const int n0  = blockIdx.y * 64;

    const int arow = tid >> 2;      // 0..63
    const int aq   = tid & 3;       // which float4 of the 16-wide K slab
    const int brow = tid >> 4;      // 0..15 (k)
    const int bn4  = tid & 15;      // which float4 along n

    float acc[8][4];
    #pragma unroll
    for (int i = 0; i < 8; ++i)
        #pragma unroll
        for (int j = 0; j < 4; ++j) acc[i][j] = 0.f;

    for (int kk = 0; kk < K; kk += 16) {
        #pragma unroll
        for (int r = 0; r < 2; ++r) {
            const int m = arow + r * 64;
            const float4 v = *reinterpret_cast<const float4*>(
                A + (size_t)(m0 + m) * K + kk + aq * 4);
            As[aq * 4 + 0][m] = v.x;
            As[aq * 4 + 1][m] = v.y;
            As[aq * 4 + 2][m] = v.z;
            As[aq * 4 + 3][m] = v.w;
        }
        *reinterpret_cast<float4*>(&Bs[brow][bn4 * 4]) =
            *reinterpret_cast<const float4*>(W + (size_t)(kk + brow) * N + n0 + bn4 * 4);
        __syncthreads();

        #pragma unroll
        for (int k = 0; k < 16; ++k) {
            float a[8], bfr[4];
            #pragma unroll
            for (int i = 0; i < 8; ++i) a[i] = As[k][ty * 8 + i];
            #pragma unroll
            for (int j = 0; j < 4; ++j) bfr[j] = Bs[k][tx * 4 + j];
            #pragma unroll
            for (int i = 0; i < 8; ++i)
                #pragma unroll
                for (int j = 0; j < 4; ++j) acc[i][j] += a[i] * bfr[j];
        }
        __syncthreads();
    }

    #pragma unroll
    for (int i = 0; i < 8; ++i) {
        const int row = m0 + ty * 8 + i;
        if (MODE == 0) {
            const int bb  = row / NQ;
            const int pos = row - bb * NQ;
            #pragma unroll
            for (int j = 0; j < 4; ++j) {
                const int col = n0 + tx * 4 + j;
                g_vt[((size_t)(bb * NH + (col >> 5)) * NQ + pos) * DH + (col & 31)]
                    = acc[i][j] + bias[col];
            }
        } else if (MODE == 1) {
            #pragma unroll
            for (int j = 0; j < 4; ++j) {
                const int col = n0 + tx * 4 + j;
                g_P[(size_t)row * NFUSED + col] = acc[i][j] + bias[col];
            }
        } else {
            #pragma unroll
            for (int j = 0; j < 4; ++j) {
                const int col = n0 + tx * 4 + j;
                Cout[(size_t)row * D + col] =
                    acc[i][j] + bias[col] + addin[(size_t)row * D + col];
            }
        }
    }
}

// ---------------- softmax + sampling-coordinate precompute ----------------
// one thread per (b,q,h)
__global__ void param_kernel(const float* __restrict__ refp) {
    int t = blockIdx.x * blockDim.x + threadIdx.x;
    if (t >= MR * NH) return;
    const int h  = t & 7;
    const int bq = t >> 3;
    const float* Prow = g_P + (size_t)bq * NFUSED;

    float lg[16];
    float mx = -1e30f;
    #pragma unroll
    for (int i = 0; i < 16; ++i) {
        lg[i] = Prow[256 + h * 16 + i];
        mx = fmaxf(mx, lg[i]);
    }
    float ssum = 0.f;
    #pragma unroll
    for (int i = 0; i < 16; ++i) {
        lg[i] = expf(lg[i] - mx);
        ssum += lg[i];
    }
    const float inv = 1.f / ssum;

    float4* outp = g_samp + (size_t)t * 16;
    #pragma unroll
    for (int l = 0; l < 4; ++l) {
        const float rx = refp[((size_t)bq * 4 + l) * 2 + 0];
        const float ry = refp[((size_t)bq * 4 + l) * 2 + 1];
        const float Wl = (float)c_LW[l];
        const float Hl = (float)c_LH[l];
        #pragma unroll
        for (int p = 0; p < 4; ++p) {
            const float ox = Prow[h * 32 + l * 8 + p * 2 + 0];
            const float oy = Prow[h * 32 + l * 8 + p * 2 + 1];
            float4 s;
            // x = loc*W - 0.5 with loc = ref + off/W  ->  ref*W + off - 0.5
            s.x = rx * Wl + ox - 0.5f;
            s.y = ry * Hl + oy - 0.5f;
            s.z = lg[l * 4 + p] * inv;
            s.w = 0.f;
            outp[l * 4 + p] = s;
        }
    }
}

// ---------------- bilinear gather + weighted accumulate ----------------
// one warp per (b,q,h); lane = channel
__global__ __launch_bounds__(256)
void sample_kernel() {
    const int gwarp = (blockIdx.x * blockDim.x + threadIdx.x) >> 5;
    const int lane  = threadIdx.x & 31;
    if (gwarp >= MR * NH) return;
    const int h  = gwarp & 7;
    const int bq = gwarp >> 3;
    const int b  = bq / NQ;

    const float4* sp = g_samp + (size_t)gwarp * 16;
    const float*  vb = g_vt + ((size_t)(b * NH + h) * NQ) * DH + lane;

    float acc = 0.f;
    #pragma unroll
    for (int l = 0; l < 4; ++l) {
        const int Wl = c_LW[l], Hl = c_LH[l], st = c_LS[l];
        #pragma unroll
        for (int p = 0; p < 4; ++p) {
            const float4 s = sp[l * 4 + p];        // warp-broadcast
            const float xf = floorf(s.x), yf = floorf(s.y);
            const int   x0 = (int)xf,     y0 = (int)yf;
            const float wx1 = s.x - xf,   wy1 = s.y - yf;
            const float wx0 = 1.f - wx1,  wy0 = 1.f - wy1;
            const int x1 = x0 + 1, y1 = y0 + 1;
            const bool vx0 = (x0 >= 0) && (x0 < Wl);
            const bool vx1 = (x1 >= 0) && (x1 < Wl);
            float c = 0.f;
            if (y0 >= 0 && y0 < Hl) {
                const float* r0 = vb + (size_t)(st + y0 * Wl) * DH;
                if (vx0) c += wx0 * wy0 * __ldg(r0 + (size_t)x0 * DH);
                if (vx1) c += wx1 * wy0 * __ldg(r0 + (size_t)x1 * DH);
            }
            if (y1 >= 0 && y1 < Hl) {
                const float* r1 = vb + (size_t)(st + y1 * Wl) * DH;
                if (vx0) c += wx0 * wy1 * __ldg(r1 + (size_t)x0 * DH);
                if (vx1) c += wx1 * wy1 * __ldg(r1 + (size_t)x1 * DH);
            }
            acc += s.z * c;
        }
    }
    g_tmp[(size_t)bq * D + h * DH + lane] = acc;
}

// ---------------- launch ----------------
extern "C" void kernel_launch(void* const* d_in, const int* in_sizes, int n_in,
                              void* d_out, int out_size) {
    const float* query = (const float*)d_in[0];
    const float* value = (const float*)d_in[1];
    const float* refp  = (const float*)d_in[2];
    // d_in[3] spatial_shapes, d_in[4] level_start_index: compile-time constants
    const float* Wv   = (const float*)d_in[5];
    const float* bv   = (const float*)d_in[6];
    const float* Wo   = (const float*)d_in[7];
    const float* bo   = (const float*)d_in[8];
    const float* Wa   = (const float*)d_in[9];
    const float* ba   = (const float*)d_in[10];
    const float* Wout = (const float*)d_in[11];
    const float* bout = (const float*)d_in[12];
    float* out = (float*)d_out;

    // 1) fuse [Wo|Wa] so query is read once
    pack_w_kernel<<<(D * NFUSED + 255) / 256, 256>>>(Wo, bo, Wa, ba);

    // 2) v = value @ Wv + bv  -> head-major layout for 128B-line gathers
    gemm_kernel<0><<<dim3(MR / 128, 256 / 64), 256>>>(value, Wv, bv, nullptr, nullptr, 256);

    // 3) [offs | logits] = query @ [Wo|Wa] + [bo|ba]
    gemm_kernel<1><<<dim3(MR / 128, NFUSED / 64), 256>>>(query, nullptr, nullptr, nullptr, nullptr, NFUSED);

    // 4) softmax + pixel coords
    param_kernel<<<(MR * NH + 255) / 256, 256>>>(refp);

    // 5) bilinear gather + weighted sum
    sample_kernel<<<(MR * NH * 32) / 256, 256>>>();

    // 6) out = tmp @ Wout + bout + query
    gemm_kernel<2><<<dim3(MR / 128, 256 / 64), 256>>>(nullptr, Wout, bout, query, out, 256);
}

// round 3
// speedup vs baseline: 1.5085x; 1.5085x over previous
#include <cuda_runtime.h>
#include <cstdint>
#include <cstddef>

// ---------------- static problem shape ----------------
constexpr int BSZ = 2;
constexpr int NQ  = 21760;
constexpr int MR  = BSZ * NQ;      // 43520 rows
constexpr int D   = 256;
constexpr int NH  = 8;
constexpr int DH  = 32;
constexpr int NFUSED = 384;        // 256 offs + 128 attn logits

__device__ __constant__ int c_LW[4] = {128, 64, 32, 16};
__device__ __constant__ int c_LH[4] = {128, 64, 32, 16};
__device__ __constant__ int c_LS[4] = {0, 16384, 20480, 21504};

// ---------------- scratch (device globals; no allocation allowed) ----------------
__device__ float  g_vt[(size_t)BSZ * NH * NQ * DH];     // v transposed: [b][h][pos][c]
__device__ float  g_P [(size_t)MR * NFUSED];            // raw offs(256) + attn logits(128)
__device__ float  g_tmp[(size_t)MR * D];                // attention output before Wout
__device__ float  g_Wf[D * NFUSED];                     // fused [Wo | Wa]
__device__ float  g_bf[NFUSED];                         // fused [bo | ba]

// ---------------- helpers ----------------
__device__ __forceinline__ uint32_t f2tf32(float x) {
    uint32_t r;
    asm("cvt.rna.tf32.f32 %0, %1;" : "=r"(r) : "f"(x));
    return r;
}

__device__ __forceinline__ void mma_tf32(float& c0, float& c1, float& c2, float& c3,
                                         uint32_t a0, uint32_t a1, uint32_t a2, uint32_t a3,
                                         uint32_t b0, uint32_t b1) {
    asm volatile(
        "mma.sync.aligned.m16n8k8.row.col.f32.tf32.tf32.f32 "
        "{%0,%1,%2,%3}, {%4,%5,%6,%7}, {%8,%9}, {%0,%1,%2,%3};"
        : "+f"(c0), "+f"(c1), "+f"(c2), "+f"(c3)
        : "r"(a0), "r"(a1), "r"(a2), "r"(a3), "r"(b0), "r"(b1));
}

// ---------------- pack fused weight ----------------
__global__ void pack_w_kernel(const float* __restrict__ Wo, const float* __restrict__ bo,
                              const float* __restrict__ Wa, const float* __restrict__ ba) {
    int i = blockIdx.x * blockDim.x + threadIdx.x;
    if (i < D * NFUSED) {
        int k = i / NFUSED, n = i % NFUSED;
        g_Wf[i] = (n < 256) ? Wo[k * 256 + n] : Wa[k * 128 + (n - 256)];
    }
    if (i < NFUSED) g_bf[i] = (i < 256) ? bo[i] : ba[i - 256];
}

// ---------------- tf32 tensor-core GEMM: C = A[M,256] @ W[256,N] + bias ----------------
// Tile: BM=128, BN=64, BK=16.  8 warps as 4(M) x 2(N), warp tile 32x32.
// MODE 0: A=value, W=Wv   -> scatter into g_vt [b][h][pos][c]
// MODE 1: A=query, W=g_Wf -> g_P row-major
// MODE 2: A=g_tmp, W=Wout -> Cout = acc + bias + addin (residual)
template<int MODE>
__global__ __launch_bounds__(256)
void gemm_tc(const float* __restrict__ Ain, const float* __restrict__ Win,
             const float* __restrict__ biasin, const float* __restrict__ addin,
             float* __restrict__ Cout, int N)
{
    constexpr int K = D;
    const float* A    = (MODE == 2) ? g_tmp : Ain;
    const float* W    = (MODE == 1) ? g_Wf  : Win;
    const float* bias = (MODE == 1) ? g_bf  : biasin;

    __shared__ float As[16][136];   // [k][m], stride 136 -> conflict-free frag loads
    __shared__ float Bs[16][72];    // [k][n], stride 72

    const int tid  = threadIdx.x;
    const int warp = tid >> 5;
    const int lane = tid & 31;
    const int wm   = (warp & 3) * 32;    // warp M offset in tile
    const int wn   = (warp >> 2) * 32;   // warp N offset in tile
    const int m0   = blockIdx.x * 128;
    const int n0   = blockIdx.y * 64;

    const int ar = tid >> 2;   // 0..63  A row within pass
    const int aq = tid & 3;    // float4 index along K
    const int br = tid >> 4;   // 0..15  B k-row
    const int bc = tid & 15;   // float4 index along N

    float c[2][4][4];
    #pragma unroll
    for (int mf = 0; mf < 2; ++mf)
        #pragma unroll
        for (int nf = 0; nf < 4; ++nf)
            #pragma unroll
            for (int i = 0; i < 4; ++i) c[mf][nf][i] = 0.f;

    for (int kk = 0; kk < K; kk += 16) {
        #pragma unroll
        for (int r = 0; r < 2; ++r) {
            const int m = ar + r * 64;
            const float4 v = *reinterpret_cast<const float4*>(
                A + (size_t)(m0 + m) * K + kk + aq * 4);
            As[aq * 4 + 0][m] = __uint_as_float(f2tf32(v.x));
            As[aq * 4 + 1][m] = __uint_as_float(f2tf32(v.y));
            As[aq * 4 + 2][m] = __uint_as_float(f2tf32(v.z));
            As[aq * 4 + 3][m] = __uint_as_float(f2tf32(v.w));
        }
        {
            const float4 v = *reinterpret_cast<const float4*>(
                W + (size_t)(kk + br) * N + n0 + bc * 4);
            float4 t;
            t.x = __uint_as_float(f2tf32(v.x));
            t.y = __uint_as_float(f2tf32(v.y));
            t.z = __uint_as_float(f2tf32(v.z));
            t.w = __uint_as_float(f2tf32(v.w));
            *reinterpret_cast<float4*>(&Bs[br][bc * 4]) = t;
        }
        __syncthreads();

        #pragma unroll
        for (int kc = 0; kc < 16; kc += 8) {
            uint32_t a[2][4], b[4][2];
            const int arow = wm + (lane >> 2);
            const int acol = kc + (lane & 3);
            #pragma unroll
            for (int mf = 0; mf < 2; ++mf) {
                const int r0 = arow + mf * 16;
                a[mf][0] = __float_as_uint(As[acol    ][r0    ]);
                a[mf][1] = __float_as_uint(As[acol    ][r0 + 8]);
                a[mf][2] = __float_as_uint(As[acol + 4][r0    ]);
                a[mf][3] = __float_as_uint(As[acol + 4][r0 + 8]);
            }
            const int bk = kc + (lane & 3);
            #pragma unroll
            for (int nf = 0; nf < 4; ++nf) {
                const int nn = wn + nf * 8 + (lane >> 2);
                b[nf][0] = __float_as_uint(Bs[bk    ][nn]);
                b[nf][1] = __float_as_uint(Bs[bk + 4][nn]);
            }
            #pragma unroll
            for (int mf = 0; mf < 2; ++mf)
                #pragma unroll
                for (int nf = 0; nf < 4; ++nf)
                    mma_tf32(c[mf][nf][0], c[mf][nf][1], c[mf][nf][2], c[mf][nf][3],
                             a[mf][0], a[mf][1], a[mf][2], a[mf][3],
                             b[nf][0], b[nf][1]);
        }
        __syncthreads();
    }

    // epilogue: thread owns rows (r0, r0+8), cols (cb, cb+1) per (mf, nf)
    #pragma unroll
    for (int mf = 0; mf < 2; ++mf) {
        #pragma unroll
        for (int nf = 0; nf < 4; ++nf) {
            const int cb = n0 + wn + nf * 8 + 2 * (lane & 3);
            const float2 b2 = *reinterpret_cast<const float2*>(bias + cb);
            #pragma unroll
            for (int half = 0; half < 2; ++half) {
                const int row = m0 + wm + mf * 16 + (lane >> 2) + half * 8;
                const float v0 = c[mf][nf][half * 2 + 0] + b2.x;
                const float v1 = c[mf][nf][half * 2 + 1] + b2.y;
                if (MODE == 0) {
                    const int bb  = row / NQ;
                    const int pos = row - bb * NQ;
                    float2* dst = reinterpret_cast<float2*>(
                        g_vt + ((size_t)(bb * NH + (cb >> 5)) * NQ + pos) * DH + (cb & 31));
                    *dst = make_float2(v0, v1);
                } else if (MODE == 1) {
                    *reinterpret_cast<float2*>(g_P + (size_t)row * NFUSED + cb)
                        = make_float2(v0, v1);
                } else {
                    const float2 q2 = *reinterpret_cast<const float2*>(
                        addin + (size_t)row * D + cb);
                    *reinterpret_cast<float2*>(Cout + (size_t)row * D + cb)
                        = make_float2(v0 + q2.x, v1 + q2.y);
                }
            }
        }
    }
}

// ---------------- fused softmax + coords + bilinear gather ----------------
// one warp per (b,q,h); lane = channel; lanes 0-15 (mirrored to 16-31) also
// own one (l,p) point each for the softmax / coordinate computation.
__global__ __launch_bounds__(256)
void sample_kernel(const float* __restrict__ refp) {
    const int gwarp = blockIdx.x * 8 + (threadIdx.x >> 5);
    const int lane  = threadIdx.x & 31;
    if (gwarp >= MR * NH) return;
    const int h  = gwarp & 7;
    const int bq = gwarp >> 3;
    const int b  = (bq >= NQ);

    const float* Prow = g_P + (size_t)bq * NFUSED;
    const int i = lane & 15;          // point index (lanes 16-31 mirror 0-15)
    const int l = i >> 2;

    // softmax over the 16 logits of this head
    float lg = Prow[256 + h * 16 + i];
    float mx = lg;
    #pragma unroll
    for (int off = 8; off; off >>= 1)
        mx = fmaxf(mx, __shfl_xor_sync(0xffffffffu, mx, off));
    float e = __expf(lg - mx);
    float ssum = e;
    #pragma unroll
    for (int off = 8; off; off >>= 1)
        ssum += __shfl_xor_sync(0xffffffffu, ssum, off);
    const float wgt = e / ssum;

    // pixel coordinates for this lane's point
    const float2 off2 = *reinterpret_cast<const float2*>(Prow + h * 32 + i * 2);
    const float2 ref2 = *reinterpret_cast<const float2*>(refp + (size_t)bq * 8 + l * 2);
    const float px = ref2.x * (float)c_LW[l] + off2.x - 0.5f;
    const float py = ref2.y * (float)c_LH[l] + off2.y - 0.5f;

    const float* vb = g_vt + ((size_t)(b * NH + h) * NQ) * DH + lane;

    float acc = 0.f;
    #pragma unroll
    for (int j = 0; j < 16; ++j) {
        const int Wl = c_LW[j >> 2], Hl = c_LH[j >> 2], st = c_LS[j >> 2];
        const float sx = __shfl_sync(0xffffffffu, px,  j);
        const float sy = __shfl_sync(0xffffffffu, py,  j);
        const float sw = __shfl_sync(0xffffffffu, wgt, j);
        const float xf = floorf(sx), yf = floorf(sy);
        const int   x0 = (int)xf,    y0 = (int)yf;
        const float wx1 = sx - xf,   wy1 = sy - yf;
        const float wx0 = 1.f - wx1, wy0 = 1.f - wy1;
        const int x1 = x0 + 1, y1 = y0 + 1;
        const bool vx0 = (x0 >= 0) && (x0 < Wl);
        const bool vx1 = (x1 >= 0) && (x1 < Wl);
        float cval = 0.f;
        if (y0 >= 0 && y0 < Hl) {
            const float* r0 = vb + (size_t)(st + y0 * Wl) * DH;
            if (vx0) cval += wx0 * wy0 * __ldg(r0 + (size_t)x0 * DH);
            if (vx1) cval += wx1 * wy0 * __ldg(r0 + (size_t)x1 * DH);
        }
        if (y1 >= 0 && y1 < Hl) {
            const float* r1 = vb + (size_t)(st + y1 * Wl) * DH;
            if (vx0) cval += wx0 * wy1 * __ldg(r1 + (size_t)x0 * DH);
            if (vx1) cval += wx1 * wy1 * __ldg(r1 + (size_t)x1 * DH);
        }
        acc += sw * cval;
    }
    g_tmp[(size_t)bq * D + h * DH + lane] = acc;
}

// ---------------- launch ----------------
extern "C" void kernel_launch(void* const* d_in, const int* in_sizes, int n_in,
                              void* d_out, int out_size) {
    const float* query = (const float*)d_in[0];
    const float* value = (const float*)d_in[1];
    const float* refp  = (const float*)d_in[2];
    const float* Wv   = (const float*)d_in[5];
    const float* bv   = (const float*)d_in[6];
    const float* Wo   = (const float*)d_in[7];
    const float* bo   = (const float*)d_in[8];
    const float* Wa   = (const float*)d_in[9];
    const float* ba   = (const float*)d_in[10];
    const float* Wout = (const float*)d_in[11];
    const float* bout = (const float*)d_in[12];
    float* out = (float*)d_out;

    pack_w_kernel<<<(D * NFUSED + 255) / 256, 256>>>(Wo, bo, Wa, ba);

    // v = value @ Wv + bv  -> head-major layout
    gemm_tc<0><<<dim3(MR / 128, 256 / 64), 256>>>(value, Wv, bv, nullptr, nullptr, 256);

    // [offs | logits] = query @ [Wo|Wa] + [bo|ba]
    gemm_tc<1><<<dim3(MR / 128, NFUSED / 64), 256>>>(query, nullptr, nullptr, nullptr, nullptr, NFUSED);

    // fused softmax + coords + bilinear gather
    sample_kernel<<<MR * NH / 8, 256>>>(refp);

    // out = tmp @ Wout + bout + query
    gemm_tc<2><<<dim3(MR / 128, 256 / 64), 256>>>(nullptr, Wout, bout, query, out, 256);
}

// round 4
// speedup vs baseline: 2.3580x; 1.5631x over previous
#include <cuda_runtime.h>
#include <cstdint>
#include <cstddef>

// ---------------- static problem shape ----------------
constexpr int BSZ = 2;
constexpr int NQ  = 21760;
constexpr int MR  = BSZ * NQ;      // 43520 rows
constexpr int D   = 256;
constexpr int NH  = 8;
constexpr int DH  = 32;
constexpr int NFUSED = 384;        // 256 offs + 128 attn logits

__device__ __constant__ int c_LW[4] = {128, 64, 32, 16};
__device__ __constant__ int c_LH[4] = {128, 64, 32, 16};
__device__ __constant__ int c_LS[4] = {0, 16384, 20480, 21504};

// ---------------- scratch (device globals; no allocation allowed) ----------------
__device__ float  g_vt[(size_t)BSZ * NH * NQ * DH];     // v transposed: [b][h][pos][c]
__device__ float  g_P [(size_t)MR * NFUSED];            // raw offs(256) + attn logits(128)
__device__ float  g_tmp[(size_t)MR * D];                // attention output before Wout
__device__ float  g_Wf[D * NFUSED];                     // fused [Wo | Wa]
__device__ float  g_bf[NFUSED];                         // fused [bo | ba]

// ---------------- helpers ----------------
__device__ __forceinline__ uint32_t f2tf32(float x) {
    uint32_t r;
    asm("cvt.rna.tf32.f32 %0, %1;" : "=r"(r) : "f"(x));
    return r;
}

__device__ __forceinline__ void mma_tf32(float& c0, float& c1, float& c2, float& c3,
                                         uint32_t a0, uint32_t a1, uint32_t a2, uint32_t a3,
                                         uint32_t b0, uint32_t b1) {
    asm volatile(
        "mma.sync.aligned.m16n8k8.row.col.f32.tf32.tf32.f32 "
        "{%0,%1,%2,%3}, {%4,%5,%6,%7}, {%8,%9}, {%0,%1,%2,%3};"
        : "+f"(c0), "+f"(c1), "+f"(c2), "+f"(c3)
        : "r"(a0), "r"(a1), "r"(a2), "r"(a3), "r"(b0), "r"(b1));
}

__device__ __forceinline__ void cp16(void* smem_dst, const void* gsrc) {
    unsigned d = (unsigned)__cvta_generic_to_shared(smem_dst);
    asm volatile("cp.async.cg.shared.global [%0], [%1], 16;" :: "r"(d), "l"(gsrc));
}

// ---------------- pack fused weight ----------------
__global__ void pack_w_kernel(const float* __restrict__ Wo, const float* __restrict__ bo,
                              const float* __restrict__ Wa, const float* __restrict__ ba) {
    int i = blockIdx.x * blockDim.x + threadIdx.x;
    if (i < D * NFUSED) {
        int k = i / NFUSED, n = i % NFUSED;
        g_Wf[i] = (n < 256) ? Wo[k * 256 + n] : Wa[k * 128 + (n - 256)];
    }
    if (i < NFUSED) g_bf[i] = (i < 256) ? bo[i] : ba[i - 256];
}

// ---------------- tf32 tensor-core GEMM, cp.async double-buffered ----------------
// Tile: BM=128, BN=64, BK=16.  8 warps as 4(M) x 2(N), warp tile 32x32.
// MODE 0: A=value, W=Wv   -> scatter into g_vt [b][h][pos][c]
// MODE 1: A=query, W=g_Wf -> g_P row-major
// MODE 2: A=g_tmp, W=Wout -> Cout = acc + bias + addin (residual)
template<int MODE>
__global__ __launch_bounds__(256)
void gemm_tc(const float* __restrict__ Ain, const float* __restrict__ Win,
             const float* __restrict__ biasin, const float* __restrict__ addin,
             float* __restrict__ Cout, int N)
{
    constexpr int K = D;
    const float* A    = (MODE == 2) ? g_tmp : Ain;
    const float* W    = (MODE == 1) ? g_Wf  : Win;
    const float* bias = (MODE == 1) ? g_bf  : biasin;

    __shared__ float As[2][128][20];   // [buf][m][k], stride 20 -> conflict-free
    __shared__ float Bs[2][16][72];    // [buf][k][n], stride 72 -> conflict-free

    const int tid  = threadIdx.x;
    const int warp = tid >> 5;
    const int lane = tid & 31;
    const int wm   = (warp & 3) * 32;
    const int wn   = (warp >> 2) * 32;
    const int m0   = blockIdx.x * 128;
    const int n0   = blockIdx.y * 64;

    const int ar = tid >> 2;   // 0..63 (and +64)
    const int aq = tid & 3;
    const int br = tid >> 4;   // 0..15
    const int bc = tid & 15;

    float c[2][4][4];
    #pragma unroll
    for (int mf = 0; mf < 2; ++mf)
        #pragma unroll
        for (int nf = 0; nf < 4; ++nf)
            #pragma unroll
            for (int i = 0; i < 4; ++i) c[mf][nf][i] = 0.f;

    auto load_stage = [&](int kt, int buf) {
        const int kk = kt * 16;
        cp16(&As[buf][ar][aq * 4],      A + (size_t)(m0 + ar) * K + kk + aq * 4);
        cp16(&As[buf][ar + 64][aq * 4], A + (size_t)(m0 + ar + 64) * K + kk + aq * 4);
        cp16(&Bs[buf][br][bc * 4],      W + (size_t)(kk + br) * N + n0 + bc * 4);
        asm volatile("cp.async.commit_group;" ::: "memory");
    };

    load_stage(0, 0);

    for (int kt = 0; kt < 16; ++kt) {
        const int buf = kt & 1;
        if (kt + 1 < 16) {
            load_stage(kt + 1, buf ^ 1);
            asm volatile("cp.async.wait_group 1;" ::: "memory");
        } else {
            asm volatile("cp.async.wait_group 0;" ::: "memory");
        }
        __syncthreads();

        #pragma unroll
        for (int kc = 0; kc < 16; kc += 8) {
            uint32_t a[2][4], b[4][2];
            const int arow = wm + (lane >> 2);
            const int acol = kc + (lane & 3);
            #pragma unroll
            for (int mf = 0; mf < 2; ++mf) {
                const int r0 = arow + mf * 16;
                a[mf][0] = f2tf32(As[buf][r0    ][acol    ]);
                a[mf][1] = f2tf32(As[buf][r0 + 8][acol    ]);
                a[mf][2] = f2tf32(As[buf][r0    ][acol + 4]);
                a[mf][3] = f2tf32(As[buf][r0 + 8][acol + 4]);
            }
            #pragma unroll
            for (int nf = 0; nf < 4; ++nf) {
                const int nn = wn + nf * 8 + (lane >> 2);
                b[nf][0] = f2tf32(Bs[buf][acol    - kc + kc][nn]); // acol == kc+(lane&3)
                b[nf][1] = f2tf32(Bs[buf][acol + 4 - kc + kc][nn]);
            }
            #pragma unroll
            for (int mf = 0; mf < 2; ++mf)
                #pragma unroll
                for (int nf = 0; nf < 4; ++nf)
                    mma_tf32(c[mf][nf][0], c[mf][nf][1], c[mf][nf][2], c[mf][nf][3],
                             a[mf][0], a[mf][1], a[mf][2], a[mf][3],
                             b[nf][0], b[nf][1]);
        }
        __syncthreads();
    }

    // epilogue
    #pragma unroll
    for (int mf = 0; mf < 2; ++mf) {
        #pragma unroll
        for (int nf = 0; nf < 4; ++nf) {
            const int cb = n0 + wn + nf * 8 + 2 * (lane & 3);
            const float2 b2 = *reinterpret_cast<const float2*>(bias + cb);
            #pragma unroll
            for (int half = 0; half < 2; ++half) {
                const int row = m0 + wm + mf * 16 + (lane >> 2) + half * 8;
                const float v0 = c[mf][nf][half * 2 + 0] + b2.x;
                const float v1 = c[mf][nf][half * 2 + 1] + b2.y;
                if (MODE == 0) {
                    const int bb  = row / NQ;
                    const int pos = row - bb * NQ;
                    float2* dst = reinterpret_cast<float2*>(
                        g_vt + ((size_t)(bb * NH + (cb >> 5)) * NQ + pos) * DH + (cb & 31));
                    *dst = make_float2(v0, v1);
                } else if (MODE == 1) {
                    *reinterpret_cast<float2*>(g_P + (size_t)row * NFUSED + cb)
                        = make_float2(v0, v1);
                } else {
                    const float2 q2 = *reinterpret_cast<const float2*>(
                        addin + (size_t)row * D + cb);
                    *reinterpret_cast<float2*>(Cout + (size_t)row * D + cb)
                        = make_float2(v0 + q2.x, v1 + q2.y);
                }
            }
        }
    }
}

// ---------------- fused softmax + coords + bilinear gather ----------------
// one warp per (b,q,h).  Stage 1: lane i (0-15) owns point i -> softmax+coords.
// Stage 2: 4 groups of 8 lanes each process one point; lane handles 4 channels
// (float4).  j loop = level (uniform).  Final xor-reduction over groups.
__global__ __launch_bounds__(256)
void sample_kernel(const float* __restrict__ refp) {
    const int gwarp = blockIdx.x * 8 + (threadIdx.x >> 5);
    const int lane  = threadIdx.x & 31;
    if (gwarp >= MR * NH) return;
    const int h  = gwarp & 7;
    const int bq = gwarp >> 3;
    const int b  = (bq >= NQ);

    const float* Prow = g_P + (size_t)bq * NFUSED;
    const int i = lane & 15;          // point index (lanes 16-31 mirror)
    const int il = i >> 2;

    // softmax over the 16 logits of this head
    float lg = Prow[256 + h * 16 + i];
    float mx = lg;
    #pragma unroll
    for (int off = 8; off; off >>= 1)
        mx = fmaxf(mx, __shfl_xor_sync(0xffffffffu, mx, off));
    float e = __expf(lg - mx);
    float ssum = e;
    #pragma unroll
    for (int off = 8; off; off >>= 1)
        ssum += __shfl_xor_sync(0xffffffffu, ssum, off);
    const float wgt = e / ssum;

    // pixel coords for this lane's point
    const float2 off2 = *reinterpret_cast<const float2*>(Prow + h * 32 + i * 2);
    const float2 ref2 = *reinterpret_cast<const float2*>(refp + (size_t)bq * 8 + il * 2);
    const float px = ref2.x * (float)c_LW[il] + off2.x - 0.5f;
    const float py = ref2.y * (float)c_LH[il] + off2.y - 0.5f;

    const int pgrp = lane >> 3;       // which point of the level this group does
    const int cq   = (lane & 7) * 4;  // channel quad
    const float* vb = g_vt + ((size_t)(b * NH + h) * NQ) * DH + cq;

    float4 acc = make_float4(0.f, 0.f, 0.f, 0.f);
    #pragma unroll
    for (int j = 0; j < 4; ++j) {     // j = level
        const int Wl = c_LW[j], Hl = c_LH[j], st = c_LS[j];
        const int p  = j * 4 + pgrp;
        const float sx = __shfl_sync(0xffffffffu, px,  p);
        const float sy = __shfl_sync(0xffffffffu, py,  p);
        const float sw = __shfl_sync(0xffffffffu, wgt, p);

        const float xf = floorf(sx), yf = floorf(sy);
        const int   x0 = (int)xf,    y0 = (int)yf;
        const float wx1 = sx - xf,   wy1 = sy - yf;
        const float wx0 = 1.f - wx1, wy0 = 1.f - wy1;
        const int x1 = x0 + 1, y1 = y0 + 1;
        const bool vx0 = (x0 >= 0) && (x0 < Wl);
        const bool vx1 = (x1 >= 0) && (x1 < Wl);
        const bool vy0 = (y0 >= 0) && (y0 < Hl);
        const bool vy1 = (y1 >= 0) && (y1 < Hl);

        const float w00 = sw * wy0 * wx0;
        const float w01 = sw * wy0 * wx1;
        const float w10 = sw * wy1 * wx0;
        const float w11 = sw * wy1 * wx1;

        float4 v00 = make_float4(0,0,0,0), v01 = v00, v10 = v00, v11 = v00;
        const float* r0 = vb + (size_t)(st + y0 * Wl) * DH;
        const float* r1 = vb + (size_t)(st + y1 * Wl) * DH;
        if (vy0 && vx0) v00 = *reinterpret_cast<const float4*>(r0 + (size_t)x0 * DH);
        if (vy0 && vx1) v01 = *reinterpret_cast<const float4*>(r0 + (size_t)x1 * DH);
        if (vy1 && vx0) v10 = *reinterpret_cast<const float4*>(r1 + (size_t)x0 * DH);
        if (vy1 && vx1) v11 = *reinterpret_cast<const float4*>(r1 + (size_t)x1 * DH);

        acc.x += w00 * v00.x + w01 * v01.x + w10 * v10.x + w11 * v11.x;
        acc.y += w00 * v00.y + w01 * v01.y + w10 * v10.y + w11 * v11.y;
        acc.z += w00 * v00.z + w01 * v01.z + w10 * v10.z + w11 * v11.z;
        acc.w += w00 * v00.w + w01 * v01.w + w10 * v10.w + w11 * v11.w;
    }

    // reduce across the 4 point-groups (lanes xor 8, 16)
    #pragma unroll
    for (int off = 8; off <= 16; off <<= 1) {
        acc.x += __shfl_xor_sync(0xffffffffu, acc.x, off);
        acc.y += __shfl_xor_sync(0xffffffffu, acc.y, off);
        acc.z += __shfl_xor_sync(0xffffffffu, acc.z, off);
        acc.w += __shfl_xor_sync(0xffffffffu, acc.w, off);
    }
    if (lane < 8)
        *reinterpret_cast<float4*>(g_tmp + (size_t)bq * D + h * DH + cq) = acc;
}

// ---------------- launch ----------------
extern "C" void kernel_launch(void* const* d_in, const int* in_sizes, int n_in,
                              void* d_out, int out_size) {
    const float* query = (const float*)d_in[0];
    const float* value = (const float*)d_in[1];
    const float* refp  = (const float*)d_in[2];
    const float* Wv   = (const float*)d_in[5];
    const float* bv   = (const float*)d_in[6];
    const float* Wo   = (const float*)d_in[7];
    const float* bo   = (const float*)d_in[8];
    const float* Wa   = (const float*)d_in[9];
    const float* ba   = (const float*)d_in[10];
    const float* Wout = (const float*)d_in[11];
    const float* bout = (const float*)d_in[12];
    float* out = (float*)d_out;

    pack_w_kernel<<<(D * NFUSED + 255) / 256, 256>>>(Wo, bo, Wa, ba);

    gemm_tc<0><<<dim3(MR / 128, 256 / 64), 256>>>(value, Wv, bv, nullptr, nullptr, 256);
    gemm_tc<1><<<dim3(MR / 128, NFUSED / 64), 256>>>(query, nullptr, nullptr, nullptr, nullptr, NFUSED);

    sample_kernel<<<MR * NH / 8, 256>>>(refp);

    gemm_tc<2><<<dim3(MR / 128, 256 / 64), 256>>>(nullptr, Wout, bout, query, out, 256);
}